// round 4
// baseline (speedup 1.0000x reference)
#include <cuda_runtime.h>

#define BATCH 32
#define NBOX 300
#define HH 1024
#define WW 1024
#define NTOT (BATCH * NBOX)            /* 9600 */
#define RPB 8                          /* rows per warp-iteration (1 row/warp) */
#define GITER 16                       /* iterations per block */
#define BAND (RPB * GITER)             /* 128 rows per block */
#define CGROUPS (HH / BAND)            /* 8 -> grid 8x32 = 256 blocks = 1 wave */
#define NT 256
#define RED_BLOCKS ((NTOT + NT - 1) / NT)  /* 38 */

// Scratch (allocation-free device globals). Transposed: [box][chunk].
__device__ float g_partial[NTOT * CGROUPS];  // 307 KB
__device__ float g_blk[RED_BLOCKS];
__device__ int   g_ctr = 0;

// trunc-toward-zero + clamp, exactly matching the reference
__device__ __forceinline__ int4 box_meta(const float4 bb) {
    int x1 = (int)((bb.x - 0.5f * bb.z) * (float)WW);
    int x2 = (int)((bb.x + 0.5f * bb.z) * (float)WW);
    int y1 = (int)((bb.y - 0.5f * bb.w) * (float)HH);
    int y2 = (int)((bb.y + 0.5f * bb.w) * (float)HH);
    x1 = min(max(x1, 0), WW - 1);
    x2 = min(max(x2, 0), WW - 1);
    y1 = min(max(y1, 0), HH - 1);
    y2 = min(max(y2, 0), HH - 1);
    return make_int4(x1, x2, y1, y2);
}

// ---------------------------------------------------------------------------
// Main kernel: persistent band of 128 rows per block (single full wave).
// grid = (CGROUPS, BATCH) = (8, 32), block = 256 (8 warps, 1 row each/iter).
// Pipeline: scan(g) -> sync -> issue loads(g+1) -> gather(g) -> sync.
// ---------------------------------------------------------------------------
__global__ __launch_bounds__(NT, 2)
void main_kernel(const float* __restrict__ seg, const float* __restrict__ boxes) {
    __shared__ __align__(16) float P[RPB][WW];   // 32 KB exclusive row prefixes

    const int t    = threadIdx.x;
    const int lane = t & 31;
    const int wid  = t >> 5;
    const int b    = blockIdx.y;
    const int Y0   = blockIdx.x * BAND;
    const int base = b * NBOX;

    // Inline box metadata (boxes array tiny -> L2 resident)
    const float4* __restrict__ bp = (const float4*)boxes;
    int4 bx0 = box_meta(bp[base + t]);                    // t < 256 < 300
    int4 bx1 = (t + NT < NBOX) ? box_meta(bp[base + t + NT])
                               : make_int4(0, 0, 0, 0);

    const float* segD = seg + (size_t)(b * 3 + 1) * HH * WW;
    const float* segF = seg + (size_t)(b * 3 + 2) * HH * WW;

    float4 dv[8], fv[8];

    // preload iteration 0: row Y0 + wid
    {
        const float4* dr = (const float4*)(segD + (size_t)(Y0 + wid) * WW);
        const float4* fr = (const float4*)(segF + (size_t)(Y0 + wid) * WW);
        #pragma unroll
        for (int i = 0; i < 8; ++i) {
            dv[i] = __ldcs(&dr[i * 32 + lane]);
            fv[i] = __ldcs(&fr[i * 32 + lane]);
        }
    }

    float a0 = 0.0f, a1 = 0.0f;

    for (int g = 0; g < GITER; ++g) {
        // ---- scan: row -> exclusive prefix in P[wid] (no block barrier) ----
        float carry = 0.0f;
        #pragma unroll
        for (int i = 0; i < 8; ++i) {
            float e0 = fv[i].x - dv[i].x;
            float e1 = fv[i].y - dv[i].y;
            float e2 = fv[i].z - dv[i].z;
            float e3 = fv[i].w - dv[i].w;
            float s0 = e0, s1 = s0 + e1, s2 = s1 + e2, s3 = s2 + e3;

            float v = s3;                        // warp inclusive scan of chunk sums
            #pragma unroll
            for (int o = 1; o < 32; o <<= 1) {
                float n = __shfl_up_sync(0xffffffffu, v, o);
                if (lane >= o) v += n;
            }
            float ex = carry + (v - s3);
            carry += __shfl_sync(0xffffffffu, v, 31);
            *(float4*)&P[wid][i * 128 + lane * 4] =
                make_float4(ex, ex + s0, ex + s1, ex + s2);
        }
        __syncthreads();

        // ---- issue next band's loads (in flight during gather) ----
        if (g + 1 < GITER) {
            const int yn = Y0 + (g + 1) * RPB + wid;
            const float4* dr = (const float4*)(segD + (size_t)yn * WW);
            const float4* fr = (const float4*)(segF + (size_t)yn * WW);
            #pragma unroll
            for (int i = 0; i < 8; ++i) {
                dv[i] = __ldcs(&dr[i * 32 + lane]);
                fv[i] = __ldcs(&fr[i * 32 + lane]);
            }
        }

        // ---- gather: box row-sums from P ----
        const int yb = Y0 + g * RPB;
        #pragma unroll
        for (int r = 0; r < RPB; ++r) {
            const int yy = yb + r;
            if (yy >= bx0.z && yy < bx0.w) a0 += P[r][bx0.y] - P[r][bx0.x];
            if (yy >= bx1.z && yy < bx1.w) a1 += P[r][bx1.y] - P[r][bx1.x];
        }
        __syncthreads();
    }

    // Transposed write: [box][chunk]; uncoalesced but fire-and-forget (~10 MB).
    g_partial[(base + t) * CGROUPS + blockIdx.x] = a0;
    if (t + NT < NBOX)
        g_partial[(base + t + NT) * CGROUPS + blockIdx.x] = a1;
}

// ---------------------------------------------------------------------------
// Reduction: per box, 8 contiguous partials = 2x LDG.128 (fully coalesced),
// relu*weight, then grid sum via last-block-done (deterministic order).
// ---------------------------------------------------------------------------
__global__ __launch_bounds__(NT)
void reduce_kernel(const float* __restrict__ boxes,
                   const float* __restrict__ conf,
                   float* __restrict__ out) {
    const int t = threadIdx.x;
    const int i = blockIdx.x * NT + t;

    float val = 0.0f;
    if (i < NTOT) {
        const float4* pp = (const float4*)&g_partial[i * CGROUPS];
        float4 p0 = pp[0];
        float4 p1 = pp[1];
        float s = ((p0.x + p0.y) + (p0.z + p0.w))
                + ((p1.x + p1.y) + (p1.z + p1.w));
        float4 bb = ((const float4*)boxes)[i];
        int4 m = box_meta(bb);
        float cf = conf[i];
        bool valid = (cf >= 0.3f) && (m.y > m.x) && (m.w > m.z);
        float area = (float)((m.w - m.z) * (m.y - m.x));
        val = valid ? fmaxf(s, 0.0f) * (cf / area) : 0.0f;
    }

    // Block reduction
    __shared__ float red[NT / 32];
    #pragma unroll
    for (int o = 16; o; o >>= 1) val += __shfl_down_sync(0xffffffffu, val, o);
    if ((t & 31) == 0) red[t >> 5] = val;
    __syncthreads();
    if (t < 32) {
        float v = (t < NT / 32) ? red[t] : 0.0f;
        #pragma unroll
        for (int o = 4; o; o >>= 1) v += __shfl_down_sync(0xffffffffu, v, o);
        if (t == 0) g_blk[blockIdx.x] = v;
    }

    // Last-block-done grid reduction
    __shared__ int amLast;
    __threadfence();
    if (t == 0) amLast = (atomicAdd(&g_ctr, 1) == gridDim.x - 1);
    __syncthreads();
    if (amLast) {
        __threadfence();
        if (t < 32) {
            float v = g_blk[t];                       // t < 32 < 38
            if (t + 32 < RED_BLOCKS) v += g_blk[t + 32];
            #pragma unroll
            for (int o = 16; o; o >>= 1) v += __shfl_down_sync(0xffffffffu, v, o);
            if (t == 0) {
                out[0] = v / (float)NTOT;
                g_ctr = 0;                            // reset for next replay
            }
        }
    }
}

extern "C" void kernel_launch(void* const* d_in, const int* in_sizes, int n_in,
                              void* d_out, int out_size) {
    const float* boxes = (const float*)d_in[0];  // (32,300,4)
    const float* conf  = (const float*)d_in[1];  // (32,300)
    const float* seg   = (const float*)d_in[2];  // (32,3,1024,1024)

    dim3 grid(CGROUPS, BATCH);
    main_kernel<<<grid, NT>>>(seg, boxes);
    reduce_kernel<<<RED_BLOCKS, NT>>>(boxes, conf, (float*)d_out);
}